// round 1
// baseline (speedup 1.0000x reference)
#include <cuda_runtime.h>
#include <cuda_bf16.h>
#include <cstdint>

// Problem constants (fixed by the dataset)
#define NNODES 50000
#define NBATCH 8
#define NEDGES 1600000
#define DFEAT  128
#define DCLASS 64
#define MROWS  (NNODES * NBATCH)   // 400000

// Scratch (device globals — no allocations allowed in kernel_launch)
__device__ float g_sup[(size_t)MROWS * DFEAT];   // support buffer (GEMM out / SpMM in)
__device__ float g_h1 [(size_t)MROWS * DFEAT];   // hidden 1
__device__ float g_h2 [(size_t)MROWS * DFEAT];   // hidden 2
__device__ int   g_rowptr[NNODES + 1];

// ---------------------------------------------------------------------------
// CSR row_ptr from sorted edge_rows: row_ptr[i] = lower_bound(rows, i)
// ---------------------------------------------------------------------------
__global__ void build_rowptr_kernel(const int* __restrict__ rows, int E,
                                    int* __restrict__ rowptr, int N) {
    int i = blockIdx.x * blockDim.x + threadIdx.x;
    if (i > N) return;
    int lo = 0, hi = E;
    while (lo < hi) {
        int mid = (lo + hi) >> 1;
        if (rows[mid] < i) lo = mid + 1; else hi = mid;
    }
    rowptr[i] = lo;
}

// ---------------------------------------------------------------------------
// SGEMM: C[M][BN] = A[M][128] * W[128][BN]   (BN = 128 or 64)
// BM=128, BK=8, 256 threads, thread tile 8 x (BN/16)
// ---------------------------------------------------------------------------
template<int BN>
__global__ __launch_bounds__(256)
void gemm_kernel(const float* __restrict__ A, const float* __restrict__ W,
                 float* __restrict__ C, int M) {
    constexpr int BM = 128, BK = 8, TM = 8, TN = BN / 16;
    __shared__ float As[BK][BM];
    __shared__ float Ws[BK][BN];

    const int tid = threadIdx.x;
    const int m0  = blockIdx.x * BM;
    const int ty  = tid >> 4;        // 0..15
    const int tx  = tid & 15;        // 0..15

    float acc[TM][TN];
#pragma unroll
    for (int i = 0; i < TM; i++)
#pragma unroll
        for (int j = 0; j < TN; j++) acc[i][j] = 0.f;

    const int arow = tid >> 1;            // 0..127
    const int acol = (tid & 1) * 4;       // 0 or 4

    for (int k0 = 0; k0 < 128; k0 += BK) {
        // A tile: 128 rows x 8 k, one float4 per thread, stored transposed
        float4 av = *reinterpret_cast<const float4*>(
            &A[(size_t)(m0 + arow) * 128 + k0 + acol]);
        As[acol + 0][arow] = av.x;
        As[acol + 1][arow] = av.y;
        As[acol + 2][arow] = av.z;
        As[acol + 3][arow] = av.w;

        // W tile: 8 k-rows x BN cols
        if (BN == 128) {
            int wk = tid >> 5;             // 0..7
            int wc = (tid & 31) * 4;       // 0..124
            *reinterpret_cast<float4*>(&Ws[wk][wc]) =
                *reinterpret_cast<const float4*>(&W[(size_t)(k0 + wk) * BN + wc]);
        } else {
            if (tid < 128) {
                int wk = tid >> 4;         // 0..7
                int wc = (tid & 15) * 4;   // 0..60
                *reinterpret_cast<float4*>(&Ws[wk][wc]) =
                    *reinterpret_cast<const float4*>(&W[(size_t)(k0 + wk) * BN + wc]);
            }
        }
        __syncthreads();

#pragma unroll
        for (int kk = 0; kk < BK; kk++) {
            float a[TM], w[TN];
#pragma unroll
            for (int i = 0; i < TM; i++) a[i] = As[kk][ty * TM + i];
#pragma unroll
            for (int j = 0; j < TN; j++) w[j] = Ws[kk][tx * TN + j];
#pragma unroll
            for (int i = 0; i < TM; i++)
#pragma unroll
                for (int j = 0; j < TN; j++) acc[i][j] += a[i] * w[j];
        }
        __syncthreads();
    }

#pragma unroll
    for (int i = 0; i < TM; i++) {
        float* crow = &C[(size_t)(m0 + ty * TM + i) * BN + tx * TN];
#pragma unroll
        for (int j = 0; j < TN; j += 4) {
            float4 v = make_float4(acc[i][j], acc[i][j + 1], acc[i][j + 2], acc[i][j + 3]);
            *reinterpret_cast<float4*>(&crow[j]) = v;
        }
    }
}

// ---------------------------------------------------------------------------
// SpMM + fused epilogue.
//   MODE 0: out = relu(agg + bias + residual)
//   MODE 1: out = sigmoid(relu(agg + bias))
// grid = (NNODES, NBATCH), block = W threads (feature dim)
// ---------------------------------------------------------------------------
template<int W, int MODE>
__global__ __launch_bounds__(W)
void spmm_kernel(const float* __restrict__ sup,
                 const int*   __restrict__ rowptr,
                 const int*   __restrict__ cols,
                 const float* __restrict__ vals,
                 const float* __restrict__ bias,
                 const float* __restrict__ res,
                 float* __restrict__ out, int N) {
    const int node = blockIdx.x;
    const int b    = blockIdx.y;
    const int t    = threadIdx.x;

    const float* supb = sup + (size_t)b * N * W;
    const int e0 = rowptr[node];
    const int e1 = rowptr[node + 1];

    float acc = 0.f;
    int e = e0;
    // 4x unroll for memory-level parallelism on the L2-bound gather
    for (; e + 4 <= e1; e += 4) {
        int   c0 = cols[e],     c1 = cols[e + 1], c2 = cols[e + 2], c3 = cols[e + 3];
        float v0 = vals[e],     v1 = vals[e + 1], v2 = vals[e + 2], v3 = vals[e + 3];
        float s0 = supb[(size_t)c0 * W + t];
        float s1 = supb[(size_t)c1 * W + t];
        float s2 = supb[(size_t)c2 * W + t];
        float s3 = supb[(size_t)c3 * W + t];
        acc += v0 * s0;
        acc += v1 * s1;
        acc += v2 * s2;
        acc += v3 * s3;
    }
    for (; e < e1; e++)
        acc += vals[e] * supb[(size_t)cols[e] * W + t];

    const size_t o = ((size_t)b * N + node) * W + t;
    float r = acc + bias[t];
    if (MODE == 0) r += res[o];
    r = fmaxf(r, 0.f);
    if (MODE == 1) r = 1.f / (1.f + __expf(-r));
    out[o] = r;
}

// ---------------------------------------------------------------------------
// Launch: 3 GCN layers
// ---------------------------------------------------------------------------
extern "C" void kernel_launch(void* const* d_in, const int* in_sizes, int n_in,
                              void* d_out, int out_size) {
    const float* x    = (const float*)d_in[0];
    const int*   rows = (const int*)  d_in[1];
    const int*   cols = (const int*)  d_in[2];
    const float* vals = (const float*)d_in[3];
    const float* W1   = (const float*)d_in[4];
    const float* b1   = (const float*)d_in[5];
    const float* W2   = (const float*)d_in[6];
    const float* b2   = (const float*)d_in[7];
    const float* W3   = (const float*)d_in[8];
    const float* b3   = (const float*)d_in[9];
    float* out = (float*)d_out;

    const int N = NNODES;
    const int E = in_sizes[1];

    float *sup, *h1, *h2; int* rp;
    cudaGetSymbolAddress((void**)&sup, g_sup);
    cudaGetSymbolAddress((void**)&h1,  g_h1);
    cudaGetSymbolAddress((void**)&h2,  g_h2);
    cudaGetSymbolAddress((void**)&rp,  g_rowptr);

    // CSR offsets from sorted edge_rows
    build_rowptr_kernel<<<(N + 256) / 256, 256>>>(rows, E, rp, N);

    const int gemm_grid = MROWS / 128;          // 3125, exact
    const dim3 spmm_grid(N, NBATCH);

    // Layer 1: h1 = relu(spmm(x @ W1) + b1 + x)
    gemm_kernel<128><<<gemm_grid, 256>>>(x, W1, sup, MROWS);
    spmm_kernel<128, 0><<<spmm_grid, 128>>>(sup, rp, cols, vals, b1, x, h1, N);

    // Layer 2: h2 = relu(spmm(h1 @ W2) + b2 + h1)
    gemm_kernel<128><<<gemm_grid, 256>>>(h1, W2, sup, MROWS);
    spmm_kernel<128, 0><<<spmm_grid, 128>>>(sup, rp, cols, vals, b2, h1, h2, N);

    // Layer 3: out = sigmoid(relu(spmm(h2 @ W3) + b3))
    gemm_kernel<64><<<gemm_grid, 256>>>(h2, W3, sup, MROWS);
    spmm_kernel<64, 1><<<spmm_grid, 64>>>(sup, rp, cols, vals, b3, nullptr, out, N);
}

// round 3
// speedup vs baseline: 1.4096x; 1.4096x over previous
#include <cuda_runtime.h>
#include <cuda_fp16.h>
#include <cuda_bf16.h>
#include <cstdint>

// Problem constants (fixed by the dataset)
#define NNODES 50000
#define NBATCH 8
#define NEDGES 1600000
#define DFEAT  128
#define DCLASS 64
#define MROWS  (NNODES * NBATCH)   // 400000

// Scratch (device globals — no allocations allowed in kernel_launch)
__device__ __half g_sup[(size_t)MROWS * DFEAT];  // support buffer (GEMM out / SpMM in), fp16
__device__ float  g_h1 [(size_t)MROWS * DFEAT];  // hidden 1 (fp32: GEMM A input next layer)
__device__ float  g_h2 [(size_t)MROWS * DFEAT];  // hidden 2
__device__ int    g_rowptr[NNODES + 1];

// ---------------------------------------------------------------------------
// CSR row_ptr from sorted edge_rows: row_ptr[i] = lower_bound(rows, i)
// ---------------------------------------------------------------------------
__global__ void build_rowptr_kernel(const int* __restrict__ rows, int E,
                                    int* __restrict__ rowptr, int N) {
    int i = blockIdx.x * blockDim.x + threadIdx.x;
    if (i > N) return;
    int lo = 0, hi = E;
    while (lo < hi) {
        int mid = (lo + hi) >> 1;
        if (rows[mid] < i) lo = mid + 1; else hi = mid;
    }
    rowptr[i] = lo;
}

// ---------------------------------------------------------------------------
// SGEMM: C[M][BN] = A[M][128] * W[128][BN]   (BN = 128 or 64), C stored fp16
// BM=128, BK=8, 256 threads, thread tile 8 x (BN/16)
// ---------------------------------------------------------------------------
template<int BN>
__global__ __launch_bounds__(256)
void gemm_kernel(const float* __restrict__ A, const float* __restrict__ W,
                 __half* __restrict__ C, int M) {
    constexpr int BM = 128, BK = 8, TM = 8, TN = BN / 16;
    __shared__ float As[BK][BM];
    __shared__ float Ws[BK][BN];

    const int tid = threadIdx.x;
    const int m0  = blockIdx.x * BM;
    const int ty  = tid >> 4;        // 0..15
    const int tx  = tid & 15;        // 0..15

    float acc[TM][TN];
#pragma unroll
    for (int i = 0; i < TM; i++)
#pragma unroll
        for (int j = 0; j < TN; j++) acc[i][j] = 0.f;

    const int arow = tid >> 1;            // 0..127
    const int acol = (tid & 1) * 4;       // 0 or 4

    for (int k0 = 0; k0 < 128; k0 += BK) {
        // A tile: 128 rows x 8 k, one float4 per thread, stored transposed
        float4 av = *reinterpret_cast<const float4*>(
            &A[(size_t)(m0 + arow) * 128 + k0 + acol]);
        As[acol + 0][arow] = av.x;
        As[acol + 1][arow] = av.y;
        As[acol + 2][arow] = av.z;
        As[acol + 3][arow] = av.w;

        // W tile: 8 k-rows x BN cols
        if (BN == 128) {
            int wk = tid >> 5;             // 0..7
            int wc = (tid & 31) * 4;       // 0..124
            *reinterpret_cast<float4*>(&Ws[wk][wc]) =
                *reinterpret_cast<const float4*>(&W[(size_t)(k0 + wk) * BN + wc]);
        } else {
            if (tid < 128) {
                int wk = tid >> 4;         // 0..7
                int wc = (tid & 15) * 4;   // 0..60
                *reinterpret_cast<float4*>(&Ws[wk][wc]) =
                    *reinterpret_cast<const float4*>(&W[(size_t)(k0 + wk) * BN + wc]);
            }
        }
        __syncthreads();

#pragma unroll
        for (int kk = 0; kk < BK; kk++) {
            float a[TM], w[TN];
#pragma unroll
            for (int i = 0; i < TM; i++) a[i] = As[kk][ty * TM + i];
#pragma unroll
            for (int j = 0; j < TN; j++) w[j] = Ws[kk][tx * TN + j];
#pragma unroll
            for (int i = 0; i < TM; i++)
#pragma unroll
                for (int j = 0; j < TN; j++) acc[i][j] += a[i] * w[j];
        }
        __syncthreads();
    }

    // Epilogue: convert to fp16, store as half2 pairs (16B per thread-row)
#pragma unroll
    for (int i = 0; i < TM; i++) {
        __half2* crow = reinterpret_cast<__half2*>(
            &C[(size_t)(m0 + ty * TM + i) * BN + tx * TN]);
#pragma unroll
        for (int j = 0; j < TN; j += 2) {
            crow[j / 2] = __halves2half2(__float2half_rn(acc[i][j]),
                                         __float2half_rn(acc[i][j + 1]));
        }
    }
}

// ---------------------------------------------------------------------------
// SpMM + fused epilogue, fp16 gather (half2 lanes), fp32 accumulate.
//   MODE 0: out = relu(agg + bias + residual)
//   MODE 1: out = sigmoid(relu(agg + bias))
// grid = (NNODES, NBATCH), block = F/2 threads (half2 per thread)
// ---------------------------------------------------------------------------
template<int F, int MODE>
__global__ __launch_bounds__(F / 2)
void spmm_kernel(const __half* __restrict__ sup,
                 const int*   __restrict__ rowptr,
                 const int*   __restrict__ cols,
                 const float* __restrict__ vals,
                 const float* __restrict__ bias,
                 const float* __restrict__ res,
                 float* __restrict__ out, int N) {
    constexpr int H = F / 2;
    const int node = blockIdx.x;
    const int b    = blockIdx.y;
    const int t    = threadIdx.x;

    const __half2* supb = reinterpret_cast<const __half2*>(sup) + (size_t)b * N * H;
    const int e0 = rowptr[node];
    const int e1 = rowptr[node + 1];

    float accx = 0.f, accy = 0.f;
    int e = e0;
    // 4x unroll for memory-level parallelism on the L2-bound gather
    for (; e + 4 <= e1; e += 4) {
        int   c0 = cols[e],     c1 = cols[e + 1], c2 = cols[e + 2], c3 = cols[e + 3];
        float v0 = vals[e],     v1 = vals[e + 1], v2 = vals[e + 2], v3 = vals[e + 3];
        float2 s0 = __half22float2(supb[(size_t)c0 * H + t]);
        float2 s1 = __half22float2(supb[(size_t)c1 * H + t]);
        float2 s2 = __half22float2(supb[(size_t)c2 * H + t]);
        float2 s3 = __half22float2(supb[(size_t)c3 * H + t]);
        accx += v0 * s0.x; accy += v0 * s0.y;
        accx += v1 * s1.x; accy += v1 * s1.y;
        accx += v2 * s2.x; accy += v2 * s2.y;
        accx += v3 * s3.x; accy += v3 * s3.y;
    }
    for (; e < e1; e++) {
        float2 s = __half22float2(supb[(size_t)cols[e] * H + t]);
        float v = vals[e];
        accx += v * s.x; accy += v * s.y;
    }

    const size_t o = ((size_t)b * N + node) * F + 2 * t;
    float rx = accx + bias[2 * t];
    float ry = accy + bias[2 * t + 1];
    if (MODE == 0) {
        const float2 rr = *reinterpret_cast<const float2*>(&res[o]);
        rx += rr.x; ry += rr.y;
    }
    rx = fmaxf(rx, 0.f);
    ry = fmaxf(ry, 0.f);
    if (MODE == 1) {
        rx = 1.f / (1.f + __expf(-rx));
        ry = 1.f / (1.f + __expf(-ry));
    }
    *reinterpret_cast<float2*>(&out[o]) = make_float2(rx, ry);
}

// ---------------------------------------------------------------------------
// Launch: 3 GCN layers
// ---------------------------------------------------------------------------
extern "C" void kernel_launch(void* const* d_in, const int* in_sizes, int n_in,
                              void* d_out, int out_size) {
    const float* x    = (const float*)d_in[0];
    const int*   rows = (const int*)  d_in[1];
    const int*   cols = (const int*)  d_in[2];
    const float* vals = (const float*)d_in[3];
    const float* W1   = (const float*)d_in[4];
    const float* b1   = (const float*)d_in[5];
    const float* W2   = (const float*)d_in[6];
    const float* b2   = (const float*)d_in[7];
    const float* W3   = (const float*)d_in[8];
    const float* b3   = (const float*)d_in[9];
    float* out = (float*)d_out;

    const int N = NNODES;
    const int E = in_sizes[1];

    __half* sup; float *h1, *h2; int* rp;
    cudaGetSymbolAddress((void**)&sup, g_sup);
    cudaGetSymbolAddress((void**)&h1,  g_h1);
    cudaGetSymbolAddress((void**)&h2,  g_h2);
    cudaGetSymbolAddress((void**)&rp,  g_rowptr);

    // CSR offsets from sorted edge_rows
    build_rowptr_kernel<<<(N + 256) / 256, 256>>>(rows, E, rp, N);

    const int gemm_grid = MROWS / 128;          // 3125, exact
    const dim3 spmm_grid(N, NBATCH);

    // Layer 1: h1 = relu(spmm(x @ W1) + b1 + x)
    gemm_kernel<128><<<gemm_grid, 256>>>(x, W1, sup, MROWS);
    spmm_kernel<128, 0><<<spmm_grid, 64>>>(sup, rp, cols, vals, b1, x, h1, N);

    // Layer 2: h2 = relu(spmm(h1 @ W2) + b2 + h1)
    gemm_kernel<128><<<gemm_grid, 256>>>(h1, W2, sup, MROWS);
    spmm_kernel<128, 0><<<spmm_grid, 64>>>(sup, rp, cols, vals, b2, h1, h2, N);

    // Layer 3: out = sigmoid(relu(spmm(h2 @ W3) + b3))
    gemm_kernel<64><<<gemm_grid, 256>>>(h2, W3, sup, MROWS);
    spmm_kernel<64, 1><<<spmm_grid, 32>>>(sup, rp, cols, vals, b3, nullptr, out, N);
}

// round 4
// speedup vs baseline: 2.6605x; 1.8874x over previous
#include <cuda_runtime.h>
#include <cuda_fp16.h>
#include <cstdint>

// Problem constants (fixed by the dataset)
#define NNODES 50000
#define NBATCH 8
#define DFEAT  128
#define DCLASS 64
#define MROWS  (NNODES * NBATCH)   // 400000

// Scratch (device globals — no allocations allowed in kernel_launch)
__device__ __half g_sup[(size_t)MROWS * DFEAT];  // GEMM out / SpMM gather src
__device__ __half g_h1 [(size_t)MROWS * DFEAT];  // hidden 1 (fp16)
__device__ __half g_h2 [(size_t)MROWS * DFEAT];  // hidden 2 (fp16)
__device__ __half g_xh [(size_t)MROWS * DFEAT];  // x converted to fp16
__device__ __half g_W1h[DFEAT * DFEAT];
__device__ __half g_W2h[DFEAT * DFEAT];
__device__ __half g_W3h[DFEAT * DCLASS];
__device__ int    g_rowptr[NNODES + 1];

static __device__ __forceinline__ uint32_t smem_u32(const void* p) {
    return (uint32_t)__cvta_generic_to_shared(p);
}

// ---------------------------------------------------------------------------
// CSR row_ptr from sorted edge_rows: row_ptr[i] = lower_bound(rows, i)
// ---------------------------------------------------------------------------
__global__ void build_rowptr_kernel(const int* __restrict__ rows, int E,
                                    int* __restrict__ rowptr, int N) {
    int i = blockIdx.x * blockDim.x + threadIdx.x;
    if (i > N) return;
    int lo = 0, hi = E;
    while (lo < hi) {
        int mid = (lo + hi) >> 1;
        if (rows[mid] < i) lo = mid + 1; else hi = mid;
    }
    rowptr[i] = lo;
}

// ---------------------------------------------------------------------------
// float -> half convert (vectorized, n divisible by 4)
// ---------------------------------------------------------------------------
__global__ void f2h_kernel(const float4* __restrict__ in, uint2* __restrict__ out,
                           int n4) {
    int stride = gridDim.x * blockDim.x;
    for (int i = blockIdx.x * blockDim.x + threadIdx.x; i < n4; i += stride) {
        float4 v = in[i];
        __half2 a = __floats2half2_rn(v.x, v.y);
        __half2 b = __floats2half2_rn(v.z, v.w);
        uint2 o;
        o.x = *reinterpret_cast<uint32_t*>(&a);
        o.y = *reinterpret_cast<uint32_t*>(&b);
        out[i] = o;
    }
}

// ---------------------------------------------------------------------------
// Tensor-core GEMM: C[M][BN] = A[M][128] * W[128][BN], fp16 in, fp32 acc,
// fp16 out. BM=128, 256 threads (8 warps as 2m x 4n), K split into 2 halves
// of 64 to keep static smem < 48KB. mma.sync.m16n8k16 + ldmatrix.
// ---------------------------------------------------------------------------
template<int BN>
__global__ __launch_bounds__(256)
void mma_gemm(const __half* __restrict__ A, const __half* __restrict__ W,
              __half* __restrict__ C) {
    constexpr int LDA = 72;        // 64 k-halves + 8 pad (144B stride: conflict-free)
    constexpr int LDB = BN + 8;    // 136 or 72
    constexpr int NT  = BN / 32;   // n-tiles (of 8) per warp: 4 or 2
    __shared__ __half As[128 * LDA];   // 18.4 KB
    __shared__ __half Bs[64 * LDB];    // 17.4 KB (BN=128) / 9.2 KB

    const int tid  = threadIdx.x;
    const int warp = tid >> 5, lane = tid & 31;
    const int wm = (warp & 1) * 64;          // warp m base (2 warps in m)
    const int wn = (warp >> 1) * (BN / 4);   // warp n base (4 warps in n)
    const size_t m0 = (size_t)blockIdx.x * 128;

    float acc[4][NT][4];
#pragma unroll
    for (int mt = 0; mt < 4; mt++)
#pragma unroll
        for (int nt = 0; nt < NT; nt++)
#pragma unroll
            for (int i = 0; i < 4; i++) acc[mt][nt][i] = 0.f;

#pragma unroll
    for (int kc = 0; kc < 2; kc++) {
        // Load A k-half: 128 rows x 64 halves = 1024 16B-chunks (4/thread)
        const __half* Agp = A + m0 * 128 + kc * 64;
#pragma unroll
        for (int i = 0; i < 4; i++) {
            int c = tid + i * 256;
            int r = c >> 3, col = (c & 7) * 8;
            *reinterpret_cast<uint4*>(&As[r * LDA + col]) =
                *reinterpret_cast<const uint4*>(&Agp[(size_t)r * 128 + col]);
        }
        // Load W k-half: 64 rows x BN halves = 64*BN/8 chunks
        constexpr int CPR = BN / 8;              // 16B chunks per row
        const __half* Wgp = W + (size_t)kc * 64 * BN;
#pragma unroll
        for (int i = 0; i < 64 * CPR / 256; i++) {
            int c = tid + i * 256;
            int r = c / CPR, col = (c % CPR) * 8;
            *reinterpret_cast<uint4*>(&Bs[r * LDB + col]) =
                *reinterpret_cast<const uint4*>(&Wgp[(size_t)r * BN + col]);
        }
        __syncthreads();

#pragma unroll
        for (int k0 = 0; k0 < 64; k0 += 16) {
            uint32_t a[4][4];
#pragma unroll
            for (int mt = 0; mt < 4; mt++) {
                int row = wm + mt * 16 + (lane & 15);
                int col = k0 + (lane >> 4) * 8;
                uint32_t ad = smem_u32(&As[row * LDA + col]);
                asm volatile(
                    "ldmatrix.sync.aligned.m8n8.x4.shared.b16 {%0,%1,%2,%3}, [%4];"
                    : "=r"(a[mt][0]), "=r"(a[mt][1]), "=r"(a[mt][2]), "=r"(a[mt][3])
                    : "r"(ad));
            }
            uint32_t b[NT][2];
#pragma unroll
            for (int nt = 0; nt < NT; nt++) {
                int row = k0 + (lane & 15);
                int col = wn + nt * 8;
                uint32_t ad = smem_u32(&Bs[row * LDB + col]);
                asm volatile(
                    "ldmatrix.sync.aligned.m8n8.x2.trans.shared.b16 {%0,%1}, [%2];"
                    : "=r"(b[nt][0]), "=r"(b[nt][1]) : "r"(ad));
            }
#pragma unroll
            for (int mt = 0; mt < 4; mt++)
#pragma unroll
                for (int nt = 0; nt < NT; nt++)
                    asm volatile(
                        "mma.sync.aligned.m16n8k16.row.col.f32.f16.f16.f32 "
                        "{%0,%1,%2,%3}, {%4,%5,%6,%7}, {%8,%9}, {%0,%1,%2,%3};"
                        : "+f"(acc[mt][nt][0]), "+f"(acc[mt][nt][1]),
                          "+f"(acc[mt][nt][2]), "+f"(acc[mt][nt][3])
                        : "r"(a[mt][0]), "r"(a[mt][1]), "r"(a[mt][2]), "r"(a[mt][3]),
                          "r"(b[nt][0]), "r"(b[nt][1]));
        }
        __syncthreads();
    }

    // Epilogue: fp32 acc -> fp16, half2 stores
    const int gid = lane >> 2, qid = lane & 3;
#pragma unroll
    for (int mt = 0; mt < 4; mt++) {
#pragma unroll
        for (int nt = 0; nt < NT; nt++) {
            int r  = wm + mt * 16 + gid;
            int cc = wn + nt * 8 + qid * 2;
            __half2 lo = __floats2half2_rn(acc[mt][nt][0], acc[mt][nt][1]);
            __half2 hi = __floats2half2_rn(acc[mt][nt][2], acc[mt][nt][3]);
            *reinterpret_cast<__half2*>(&C[(m0 + r) * BN + cc]) = lo;
            *reinterpret_cast<__half2*>(&C[(m0 + r + 8) * BN + cc]) = hi;
        }
    }
}

// ---------------------------------------------------------------------------
// SpMM + fused epilogue. One warp per (node, batch), 4 warps/block.
//   F=128: each lane loads 8B (2 half2) per edge -> 1 LDG.64 per warp-edge
//   F=64 : each lane loads 4B (1 half2)
//   MODE 0: h_out(fp16) = relu(agg + bias + res(fp16))
//   MODE 1: out(fp32)   = sigmoid(relu(agg + bias))
// grid = (NNODES, NBATCH/4), block = 128
// ---------------------------------------------------------------------------
template<int F, int MODE>
__global__ __launch_bounds__(128)
void spmm_kernel(const __half* __restrict__ sup,
                 const int*   __restrict__ rowptr,
                 const int*   __restrict__ cols,
                 const float* __restrict__ vals,
                 const float* __restrict__ bias,
                 const __half* __restrict__ res,
                 void* __restrict__ out, int N) {
    constexpr int H = F / 2;                 // half2 per row
    const int node = blockIdx.x;
    const int b    = blockIdx.y * 4 + (threadIdx.x >> 5);
    const int t    = threadIdx.x & 31;

    const __half2* supb = reinterpret_cast<const __half2*>(sup) + (size_t)b * N * H;
    const int e0 = rowptr[node];
    const int e1 = rowptr[node + 1];

    if (F == 128) {
        float a0 = 0.f, a1 = 0.f, a2 = 0.f, a3 = 0.f;
        int e = e0;
        for (; e + 4 <= e1; e += 4) {
            int   c0 = cols[e],  c1 = cols[e + 1], c2 = cols[e + 2], c3 = cols[e + 3];
            float v0 = vals[e],  v1 = vals[e + 1], v2 = vals[e + 2], v3 = vals[e + 3];
            uint2 u0 = *reinterpret_cast<const uint2*>(supb + (size_t)c0 * H + 2 * t);
            uint2 u1 = *reinterpret_cast<const uint2*>(supb + (size_t)c1 * H + 2 * t);
            uint2 u2 = *reinterpret_cast<const uint2*>(supb + (size_t)c2 * H + 2 * t);
            uint2 u3 = *reinterpret_cast<const uint2*>(supb + (size_t)c3 * H + 2 * t);
            float2 p, q;
            p = __half22float2(*reinterpret_cast<__half2*>(&u0.x));
            q = __half22float2(*reinterpret_cast<__half2*>(&u0.y));
            a0 += v0 * p.x; a1 += v0 * p.y; a2 += v0 * q.x; a3 += v0 * q.y;
            p = __half22float2(*reinterpret_cast<__half2*>(&u1.x));
            q = __half22float2(*reinterpret_cast<__half2*>(&u1.y));
            a0 += v1 * p.x; a1 += v1 * p.y; a2 += v1 * q.x; a3 += v1 * q.y;
            p = __half22float2(*reinterpret_cast<__half2*>(&u2.x));
            q = __half22float2(*reinterpret_cast<__half2*>(&u2.y));
            a0 += v2 * p.x; a1 += v2 * p.y; a2 += v2 * q.x; a3 += v2 * q.y;
            p = __half22float2(*reinterpret_cast<__half2*>(&u3.x));
            q = __half22float2(*reinterpret_cast<__half2*>(&u3.y));
            a0 += v3 * p.x; a1 += v3 * p.y; a2 += v3 * q.x; a3 += v3 * q.y;
        }
        for (; e < e1; e++) {
            float v = vals[e];
            uint2 u = *reinterpret_cast<const uint2*>(supb + (size_t)cols[e] * H + 2 * t);
            float2 p = __half22float2(*reinterpret_cast<__half2*>(&u.x));
            float2 q = __half22float2(*reinterpret_cast<__half2*>(&u.y));
            a0 += v * p.x; a1 += v * p.y; a2 += v * q.x; a3 += v * q.y;
        }
        float4 bi = *reinterpret_cast<const float4*>(&bias[4 * t]);
        a0 += bi.x; a1 += bi.y; a2 += bi.z; a3 += bi.w;
        const size_t o2 = ((size_t)b * N + node) * H + 2 * t;  // in half2 units
        // residual (fp16)
        uint2 rv = *reinterpret_cast<const uint2*>(
            reinterpret_cast<const __half2*>(res) + o2);
        float2 rp = __half22float2(*reinterpret_cast<__half2*>(&rv.x));
        float2 rq = __half22float2(*reinterpret_cast<__half2*>(&rv.y));
        a0 = fmaxf(a0 + rp.x, 0.f);
        a1 = fmaxf(a1 + rp.y, 0.f);
        a2 = fmaxf(a2 + rq.x, 0.f);
        a3 = fmaxf(a3 + rq.y, 0.f);
        __half2 o01 = __floats2half2_rn(a0, a1);
        __half2 o23 = __floats2half2_rn(a2, a3);
        uint2 ov;
        ov.x = *reinterpret_cast<uint32_t*>(&o01);
        ov.y = *reinterpret_cast<uint32_t*>(&o23);
        *reinterpret_cast<uint2*>(reinterpret_cast<__half2*>(out) + o2) = ov;
    } else {
        // F == 64, MODE 1 (final layer, fp32 out + sigmoid)
        float a0 = 0.f, a1 = 0.f;
        int e = e0;
        for (; e + 4 <= e1; e += 4) {
            int   c0 = cols[e],  c1 = cols[e + 1], c2 = cols[e + 2], c3 = cols[e + 3];
            float v0 = vals[e],  v1 = vals[e + 1], v2 = vals[e + 2], v3 = vals[e + 3];
            float2 s0 = __half22float2(supb[(size_t)c0 * H + t]);
            float2 s1 = __half22float2(supb[(size_t)c1 * H + t]);
            float2 s2 = __half22float2(supb[(size_t)c2 * H + t]);
            float2 s3 = __half22float2(supb[(size_t)c3 * H + t]);
            a0 += v0 * s0.x; a1 += v0 * s0.y;
            a0 += v1 * s1.x; a1 += v1 * s1.y;
            a0 += v2 * s2.x; a1 += v2 * s2.y;
            a0 += v3 * s3.x; a1 += v3 * s3.y;
        }
        for (; e < e1; e++) {
            float v = vals[e];
            float2 s = __half22float2(supb[(size_t)cols[e] * H + t]);
            a0 += v * s.x; a1 += v * s.y;
        }
        float2 bi = *reinterpret_cast<const float2*>(&bias[2 * t]);
        a0 = fmaxf(a0 + bi.x, 0.f);
        a1 = fmaxf(a1 + bi.y, 0.f);
        a0 = 1.f / (1.f + __expf(-a0));
        a1 = 1.f / (1.f + __expf(-a1));
        const size_t o = ((size_t)b * N + node) * F + 2 * t;
        *reinterpret_cast<float2*>(reinterpret_cast<float*>(out) + o) =
            make_float2(a0, a1);
    }
}

// ---------------------------------------------------------------------------
// Launch: convert + 3 GCN layers
// ---------------------------------------------------------------------------
extern "C" void kernel_launch(void* const* d_in, const int* in_sizes, int n_in,
                              void* d_out, int out_size) {
    const float* x    = (const float*)d_in[0];
    const int*   rows = (const int*)  d_in[1];
    const int*   cols = (const int*)  d_in[2];
    const float* vals = (const float*)d_in[3];
    const float* W1   = (const float*)d_in[4];
    const float* b1   = (const float*)d_in[5];
    const float* W2   = (const float*)d_in[6];
    const float* b2   = (const float*)d_in[7];
    const float* W3   = (const float*)d_in[8];
    const float* b3   = (const float*)d_in[9];
    float* out = (float*)d_out;

    const int N = NNODES;
    const int E = in_sizes[1];

    __half *sup, *h1, *h2, *xh, *w1h, *w2h, *w3h; int* rp;
    cudaGetSymbolAddress((void**)&sup, g_sup);
    cudaGetSymbolAddress((void**)&h1,  g_h1);
    cudaGetSymbolAddress((void**)&h2,  g_h2);
    cudaGetSymbolAddress((void**)&xh,  g_xh);
    cudaGetSymbolAddress((void**)&w1h, g_W1h);
    cudaGetSymbolAddress((void**)&w2h, g_W2h);
    cudaGetSymbolAddress((void**)&w3h, g_W3h);
    cudaGetSymbolAddress((void**)&rp,  g_rowptr);

    // Prep: CSR offsets + fp16 conversions
    build_rowptr_kernel<<<(N + 256) / 256, 256>>>(rows, E, rp, N);
    f2h_kernel<<<2048, 256>>>((const float4*)x, (uint2*)xh, MROWS * DFEAT / 4);
    f2h_kernel<<<16, 256>>>((const float4*)W1, (uint2*)w1h, DFEAT * DFEAT / 4);
    f2h_kernel<<<16, 256>>>((const float4*)W2, (uint2*)w2h, DFEAT * DFEAT / 4);
    f2h_kernel<<<8,  256>>>((const float4*)W3, (uint2*)w3h, DFEAT * DCLASS / 4);

    const int gemm_grid = MROWS / 128;          // 3125, exact
    const dim3 spmm_grid(N, NBATCH / 4);

    // Layer 1: h1 = relu(spmm(x @ W1) + b1 + x)
    mma_gemm<128><<<gemm_grid, 256>>>(xh, w1h, sup);
    spmm_kernel<128, 0><<<spmm_grid, 128>>>(sup, rp, cols, vals, b1, xh, h1, N);

    // Layer 2: h2 = relu(spmm(h1 @ W2) + b2 + h1)
    mma_gemm<128><<<gemm_grid, 256>>>(h1, w2h, sup);
    spmm_kernel<128, 0><<<spmm_grid, 128>>>(sup, rp, cols, vals, b2, h1, h2, N);

    // Layer 3: out = sigmoid(relu(spmm(h2 @ W3) + b3))
    mma_gemm<64><<<gemm_grid, 256>>>(h2, w3h, sup);
    spmm_kernel<64, 1><<<spmm_grid, 128>>>(sup, rp, cols, vals, b3, nullptr, out, N);
}